// round 4
// baseline (speedup 1.0000x reference)
#include <cuda_runtime.h>

#define CC   128
#define BKT  8192
#define NMAX 500000

// ---------------- scratch (__device__ globals; no allocs allowed) ----------
__device__ float    g_q[(size_t)NMAX * CC];      // 256 MB
__device__ float    g_xsum[BKT * CC];
__device__ unsigned g_kkey[BKT * CC];
__device__ unsigned g_vkey[BKT * CC];
__device__ float    g_counts[BKT];
__device__ float    g_kc[BKT * 2 * CC];          // [mean | max]
__device__ float    g_vc[BKT * 2 * CC];
__device__ unsigned g_or;                        // 0 => ids are int64

// monotonic float<->uint mapping for atomicMax on floats
__device__ __forceinline__ unsigned fenc(float f) {
    unsigned u = __float_as_uint(f);
    return (u & 0x80000000u) ? ~u : (u | 0x80000000u);
}
__device__ __forceinline__ float fdec(unsigned e) {
    return (e & 0x80000000u) ? __uint_as_float(e ^ 0x80000000u)
                             : __uint_as_float(~e);
}
__device__ __forceinline__ int get_id(const void* ids, int i, bool is64) {
    return is64 ? (int)((const long long*)ids)[i] : ((const int*)ids)[i];
}

// ---------------- init ------------------------------------------------------
__global__ void k_init() {
    size_t i = (size_t)blockIdx.x * blockDim.x + threadIdx.x;
    size_t stride = (size_t)gridDim.x * blockDim.x;
    for (size_t t = i; t < (size_t)BKT * CC; t += stride) {
        g_xsum[t] = 0.0f; g_kkey[t] = 0u; g_vkey[t] = 0u;
    }
    for (size_t t = i; t < BKT; t += stride) g_counts[t] = 0.0f;
    if (i == 0) g_or = 0u;
}

// ---------------- id dtype detection ---------------------------------------
// Read only the first nwords 32-bit words (safe for both int32 and int64).
// If int64: odd words are high halves of ids[0..n/2) == 0 (ids < 8192).
// If int32: odd words are random ids in [0,8192) -> OR is nonzero w.h.p. 1.
__global__ void k_detect(const unsigned* __restrict__ w, int nwords) {
    unsigned acc = 0;
    int gid = blockIdx.x * blockDim.x + threadIdx.x;
    int stride = gridDim.x * blockDim.x;
    for (int t = 1 + 2 * gid; t < nwords; t += 2 * stride) acc |= w[t];
    for (int o = 16; o; o >>= 1) acc |= __shfl_xor_sync(0xFFFFFFFFu, acc, o);
    if ((threadIdx.x & 31) == 0 && acc) atomicOr(&g_or, acc);
}

// ---------------- phase 1: qkv GEMM + reductions ----------------------------
// tile 128 rows x 128 cols, 256 threads, thread computes 8x8.
// xsT: transposed x tile [k][r], stride 129 (conflict-free per-k row reads).
// ws : weight tile [k][c], stride 132 (16B-aligned rows for float4).
__global__ void __launch_bounds__(256)
k_qkv(const float* __restrict__ x, const void* __restrict__ ids,
      const float* __restrict__ Wq, const float* __restrict__ bq,
      const float* __restrict__ Wk, const float* __restrict__ bk,
      const float* __restrict__ Wv, const float* __restrict__ bv, int n) {
    extern __shared__ float sm[];
    float* xsT = sm;               // 128*129
    float* ws  = sm + 128 * 129;   // 128*132
    __shared__ int ids_s[128];

    const bool is64 = (g_or == 0u);
    const int tid = threadIdx.x;
    const int row0 = blockIdx.x * 128;

    if (tid < 128) {
        int r = row0 + tid;
        ids_s[tid] = (r < n) ? get_id(ids, r, is64) : 0;
    }
    for (int t = tid; t < 128 * 32; t += 256) {
        int r = t >> 5, c4 = t & 31;
        float4 v = make_float4(0.f, 0.f, 0.f, 0.f);
        if (row0 + r < n) v = ((const float4*)x)[(size_t)(row0 + r) * 32 + c4];
        xsT[(c4 * 4 + 0) * 129 + r] = v.x;
        xsT[(c4 * 4 + 1) * 129 + r] = v.y;
        xsT[(c4 * 4 + 2) * 129 + r] = v.z;
        xsT[(c4 * 4 + 3) * 129 + r] = v.w;
    }

    const int rT = tid >> 4;          // 0..15, rows rT + 16*i
    const int c0 = (tid & 15) * 8;    // 8 cols
    const float* Ws[3] = {Wq, Wk, Wv};
    const float* Bs[3] = {bq, bk, bv};

    for (int mm = 0; mm < 3; mm++) {
        __syncthreads();   // prior reads of ws done; also covers tile loads on mm==0
        for (int t = tid; t < 128 * 32; t += 256) {
            int r = t >> 5, c4 = t & 31;
            ((float4*)&ws[r * 132])[c4] = ((const float4*)Ws[mm])[r * 32 + c4];
        }
        __syncthreads();

        float acc[8][8];
        #pragma unroll
        for (int i = 0; i < 8; i++)
            #pragma unroll
            for (int j = 0; j < 8; j++) acc[i][j] = 0.0f;

        for (int k = 0; k < 128; k++) {
            float xv[8];
            #pragma unroll
            for (int i = 0; i < 8; i++) xv[i] = xsT[k * 129 + rT + 16 * i];
            float4 w0 = *(const float4*)&ws[k * 132 + c0];
            float4 w1 = *(const float4*)&ws[k * 132 + c0 + 4];
            float wr[8] = {w0.x, w0.y, w0.z, w0.w, w1.x, w1.y, w1.z, w1.w};
            #pragma unroll
            for (int i = 0; i < 8; i++)
                #pragma unroll
                for (int j = 0; j < 8; j++)
                    acc[i][j] = fmaf(xv[i], wr[j], acc[i][j]);
        }

        float bb[8];
        #pragma unroll
        for (int j = 0; j < 8; j++) bb[j] = __ldg(&Bs[mm][c0 + j]);
        #pragma unroll
        for (int i = 0; i < 8; i++)
            #pragma unroll
            for (int j = 0; j < 8; j++) acc[i][j] += bb[j];

        if (mm == 0) {
            #pragma unroll
            for (int i = 0; i < 8; i++) {
                int r = rT + 16 * i, grow = row0 + r;
                if (grow < n) {
                    float4 o0 = make_float4(acc[i][0], acc[i][1], acc[i][2], acc[i][3]);
                    float4 o1 = make_float4(acc[i][4], acc[i][5], acc[i][6], acc[i][7]);
                    *(float4*)&g_q[(size_t)grow * 128 + c0]     = o0;
                    *(float4*)&g_q[(size_t)grow * 128 + c0 + 4] = o1;
                }
            }
        } else {
            unsigned* keys = (mm == 1) ? g_kkey : g_vkey;
            #pragma unroll
            for (int i = 0; i < 8; i++) {
                int r = rT + 16 * i;
                if (row0 + r < n) {
                    unsigned* p = keys + (size_t)ids_s[r] * 128 + c0;
                    #pragma unroll
                    for (int j = 0; j < 8; j++) atomicMax(&p[j], fenc(acc[i][j]));
                }
            }
        }
    }

    // counts + x_sum (xsT untouched by ws reloads)
    #pragma unroll
    for (int i = 0; i < 8; i++) {
        int r = rT + 16 * i;
        if (row0 + r < n) {
            int b = ids_s[r];
            #pragma unroll
            for (int j = 0; j < 8; j++)
                atomicAdd(&g_xsum[(size_t)b * 128 + c0 + j], xsT[(c0 + j) * 129 + r]);
            if (c0 == 0) atomicAdd(&g_counts[b], 1.0f);
        }
    }
}

// ---------------- phase 2: centroid finalize --------------------------------
// k_sum[b] = x_sum[b] @ Wk + counts[b]*bk (linearity); means + decoded maxes.
__global__ void __launch_bounds__(256)
k_cent(const float* __restrict__ Wk, const float* __restrict__ bk,
       const float* __restrict__ Wv, const float* __restrict__ bv) {
    int t = blockIdx.x * 256 + threadIdx.x;
    if (t >= BKT * CC) return;
    int b = t >> 7, c = t & 127;
    float cnt = g_counts[b];
    float inv = 1.0f / fmaxf(cnt, 1.0f);
    const float* xs = &g_xsum[(size_t)b * 128];
    float ak = 0.0f, av = 0.0f;
    #pragma unroll 4
    for (int k = 0; k < 128; k++) {
        float xv = xs[k];
        ak = fmaf(xv, Wk[k * 128 + c], ak);
        av = fmaf(xv, Wv[k * 128 + c], av);
    }
    g_kc[(size_t)b * 256 + c] = (ak + cnt * __ldg(&bk[c])) * inv;
    g_vc[(size_t)b * 256 + c] = (av + cnt * __ldg(&bv[c])) * inv;
    bool ne = cnt > 0.0f;
    g_kc[(size_t)b * 256 + 128 + c] = ne ? fdec(g_kkey[(size_t)b * 128 + c]) : 0.0f;
    g_vc[(size_t)b * 256 + 128 + c] = ne ? fdec(g_vkey[(size_t)b * 128 + c]) : 0.0f;
}

// ---------------- phase 3: fused gate/output chain --------------------------
// tile 64 rows, 256 threads; thread = 8 rows x 4 cols (rows rT+8i, broadcast LDS).
// smem: inter(64x260) | vctx(64x260) | h1(64x132) | wst(64x132) = 200704 B.
__global__ void __launch_bounds__(256)
k_fused(const void* __restrict__ ids,
        const float* __restrict__ Wg1, const float* __restrict__ bg1,
        const float* __restrict__ Wg2, const float* __restrict__ bg2,
        const float* __restrict__ Wvc, const float* __restrict__ bvc,
        const float* __restrict__ Wp,  const float* __restrict__ bp,
        float* __restrict__ out, int n) {
    extern __shared__ float sm[];
    float* inter = sm;                  // 64*260
    float* vctx  = sm + 64 * 260;       // 64*260
    float* h1    = vctx + 64 * 260;     // 64*132
    float* wst   = h1 + 64 * 132;       // 64*132
    __shared__ int ids_s[64];

    const bool is64 = (g_or == 0u);
    const int tid = threadIdx.x;
    const int row0 = blockIdx.x * 64;
    const float scale = 0.17677669529663687f;   // (128/4)^-0.5

    if (tid < 64) {
        int r = row0 + tid;
        ids_s[tid] = (r < n) ? get_id(ids, r, is64) : -1;
    }
    __syncthreads();

    // stage a: inter = [q,q]*kctx*scale ; vctx gather
    for (int t = tid; t < 64 * 64; t += 256) {
        int r = t >> 6, c4 = t & 63;
        int b = ids_s[r];
        float4 iv = make_float4(0.f, 0.f, 0.f, 0.f), vv = iv;
        if (b >= 0) {
            float4 qv = ((const float4*)g_q)[(size_t)(row0 + r) * 32 + (c4 & 31)];
            float4 kc = ((const float4*)g_kc)[(size_t)b * 64 + c4];
            vv        = ((const float4*)g_vc)[(size_t)b * 64 + c4];
            iv.x = qv.x * kc.x * scale; iv.y = qv.y * kc.y * scale;
            iv.z = qv.z * kc.z * scale; iv.w = qv.w * kc.w * scale;
        }
        *(float4*)&inter[r * 260 + c4 * 4] = iv;
        *(float4*)&vctx[r * 260 + c4 * 4]  = vv;
    }

    const int rT = tid >> 5;          // 0..7, rows rT + 8*i
    const int c0 = (tid & 31) * 4;    // 4 cols

    // stage b: h1 = relu(inter @ Wg1 + bg1), K=256 in 4 chunks
    float acc[8][4];
    #pragma unroll
    for (int i = 0; i < 8; i++)
        #pragma unroll
        for (int j = 0; j < 4; j++) acc[i][j] = 0.0f;
    for (int kb = 0; kb < 4; kb++) {
        __syncthreads();
        for (int t = tid; t < 64 * 32; t += 256) {
            int r = t >> 5, c4 = t & 31;
            ((float4*)&wst[r * 132])[c4] = ((const float4*)Wg1)[(kb * 64 + r) * 32 + c4];
        }
        __syncthreads();
        for (int kk = 0; kk < 64; kk++) {
            int k = kb * 64 + kk;
            float4 w = *(const float4*)&wst[kk * 132 + c0];
            #pragma unroll
            for (int i = 0; i < 8; i++) {
                float xv = inter[(rT + 8 * i) * 260 + k];
                acc[i][0] = fmaf(xv, w.x, acc[i][0]);
                acc[i][1] = fmaf(xv, w.y, acc[i][1]);
                acc[i][2] = fmaf(xv, w.z, acc[i][2]);
                acc[i][3] = fmaf(xv, w.w, acc[i][3]);
            }
        }
    }
    {
        float bb[4];
        #pragma unroll
        for (int j = 0; j < 4; j++) bb[j] = __ldg(&bg1[c0 + j]);
        #pragma unroll
        for (int i = 0; i < 8; i++)
            #pragma unroll
            for (int j = 0; j < 4; j++)
                h1[(rT + 8 * i) * 132 + c0 + j] = fmaxf(acc[i][j] + bb[j], 0.0f);
    }

    // stage c: vacc = vctx @ Wvc + bvc (kept in registers), K=256 in 4 chunks
    float vacc[8][4];
    #pragma unroll
    for (int i = 0; i < 8; i++)
        #pragma unroll
        for (int j = 0; j < 4; j++) vacc[i][j] = 0.0f;
    for (int kb = 0; kb < 4; kb++) {
        __syncthreads();
        for (int t = tid; t < 64 * 32; t += 256) {
            int r = t >> 5, c4 = t & 31;
            ((float4*)&wst[r * 132])[c4] = ((const float4*)Wvc)[(kb * 64 + r) * 32 + c4];
        }
        __syncthreads();
        for (int kk = 0; kk < 64; kk++) {
            int k = kb * 64 + kk;
            float4 w = *(const float4*)&wst[kk * 132 + c0];
            #pragma unroll
            for (int i = 0; i < 8; i++) {
                float xv = vctx[(rT + 8 * i) * 260 + k];
                vacc[i][0] = fmaf(xv, w.x, vacc[i][0]);
                vacc[i][1] = fmaf(xv, w.y, vacc[i][1]);
                vacc[i][2] = fmaf(xv, w.z, vacc[i][2]);
                vacc[i][3] = fmaf(xv, w.w, vacc[i][3]);
            }
        }
    }
    {
        float bb[4];
        #pragma unroll
        for (int j = 0; j < 4; j++) bb[j] = __ldg(&bvc[c0 + j]);
        #pragma unroll
        for (int i = 0; i < 8; i++)
            #pragma unroll
            for (int j = 0; j < 4; j++) vacc[i][j] += bb[j];
    }

    // stage d: gate = sigmoid(h1 @ Wg2 + bg2); combine with vacc
    float gacc[8][4];
    #pragma unroll
    for (int i = 0; i < 8; i++)
        #pragma unroll
        for (int j = 0; j < 4; j++) gacc[i][j] = 0.0f;
    for (int kb = 0; kb < 2; kb++) {
        __syncthreads();
        for (int t = tid; t < 64 * 32; t += 256) {
            int r = t >> 5, c4 = t & 31;
            ((float4*)&wst[r * 132])[c4] = ((const float4*)Wg2)[(kb * 64 + r) * 32 + c4];
        }
        __syncthreads();
        for (int kk = 0; kk < 64; kk++) {
            int k = kb * 64 + kk;
            float4 w = *(const float4*)&wst[kk * 132 + c0];
            #pragma unroll
            for (int i = 0; i < 8; i++) {
                float xv = h1[(rT + 8 * i) * 132 + k];
                gacc[i][0] = fmaf(xv, w.x, gacc[i][0]);
                gacc[i][1] = fmaf(xv, w.y, gacc[i][1]);
                gacc[i][2] = fmaf(xv, w.z, gacc[i][2]);
                gacc[i][3] = fmaf(xv, w.w, gacc[i][3]);
            }
        }
    }
    {
        float bb[4];
        #pragma unroll
        for (int j = 0; j < 4; j++) bb[j] = __ldg(&bg2[c0 + j]);
        __syncthreads();   // all wst/inter reads done; inter region is free now
        #pragma unroll
        for (int i = 0; i < 8; i++)
            #pragma unroll
            for (int j = 0; j < 4; j++) {
                float gate = 1.0f / (1.0f + __expf(-(gacc[i][j] + bb[j])));
                inter[(rT + 8 * i) * 260 + c0 + j] = gate * vacc[i][j];  // tbuf
            }
    }

    // stage e: out = tbuf @ Wp + bp
    float oacc[8][4];
    #pragma unroll
    for (int i = 0; i < 8; i++)
        #pragma unroll
        for (int j = 0; j < 4; j++) oacc[i][j] = 0.0f;
    for (int kb = 0; kb < 2; kb++) {
        __syncthreads();
        for (int t = tid; t < 64 * 32; t += 256) {
            int r = t >> 5, c4 = t & 31;
            ((float4*)&wst[r * 132])[c4] = ((const float4*)Wp)[(kb * 64 + r) * 32 + c4];
        }
        __syncthreads();
        for (int kk = 0; kk < 64; kk++) {
            int k = kb * 64 + kk;
            float4 w = *(const float4*)&wst[kk * 132 + c0];
            #pragma unroll
            for (int i = 0; i < 8; i++) {
                float xv = inter[(rT + 8 * i) * 260 + k];
                oacc[i][0] = fmaf(xv, w.x, oacc[i][0]);
                oacc[i][1] = fmaf(xv, w.y, oacc[i][1]);
                oacc[i][2] = fmaf(xv, w.z, oacc[i][2]);
                oacc[i][3] = fmaf(xv, w.w, oacc[i][3]);
            }
        }
    }
    {
        float bb[4];
        #pragma unroll
        for (int j = 0; j < 4; j++) bb[j] = __ldg(&bp[c0 + j]);
        #pragma unroll
        for (int i = 0; i < 8; i++) {
            int grow = row0 + rT + 8 * i;
            if (grow < n) {
                float4 o = make_float4(oacc[i][0] + bb[0], oacc[i][1] + bb[1],
                                       oacc[i][2] + bb[2], oacc[i][3] + bb[3]);
                *(float4*)&out[(size_t)grow * 128 + c0] = o;
            }
        }
    }
}

// ---------------- launch ----------------------------------------------------
extern "C" void kernel_launch(void* const* d_in, const int* in_sizes, int n_in,
                              void* d_out, int out_size) {
    const float* x   = (const float*)d_in[0];
    const void*  ids = d_in[1];
    // d_in[2] = total_buckets (constant 8192, unused)
    const float *Wq = (const float*)d_in[3],  *bq = (const float*)d_in[4];
    const float *Wk = (const float*)d_in[5],  *bk = (const float*)d_in[6];
    const float *Wv = (const float*)d_in[7],  *bv = (const float*)d_in[8];
    const float *Wg1 = (const float*)d_in[9], *bg1 = (const float*)d_in[10];
    const float *Wg2 = (const float*)d_in[11], *bg2 = (const float*)d_in[12];
    const float *Wvc = (const float*)d_in[13], *bvc = (const float*)d_in[14];
    const float *Wp  = (const float*)d_in[15], *bp  = (const float*)d_in[16];
    float* out = (float*)d_out;

    const int n = in_sizes[0] / CC;

    static int smem_set = 0;
    if (!smem_set) {
        cudaFuncSetAttribute(k_qkv,   cudaFuncAttributeMaxDynamicSharedMemorySize, 133632);
        cudaFuncSetAttribute(k_fused, cudaFuncAttributeMaxDynamicSharedMemorySize, 200704);
        smem_set = 1;
    }

    k_init<<<512, 256>>>();
    k_detect<<<256, 256>>>((const unsigned*)ids, in_sizes[1]);

    int g1 = (n + 127) / 128;
    k_qkv<<<g1, 256, 133632>>>(x, ids, Wq, bq, Wk, bk, Wv, bv, n);

    k_cent<<<(BKT * CC) / 256, 256>>>(Wk, bk, Wv, bv);

    int g3 = (n + 63) / 64;
    k_fused<<<g3, 256, 200704>>>(ids, Wg1, bg1, Wg2, bg2, Wvc, bvc, Wp, bp, out, n);
}